// round 17
// baseline (speedup 1.0000x reference)
#include <cuda_runtime.h>
#include <cstdint>

#define NN     256
#define BB     8
#define SS     14
#define BS     (BB*SS)
#define NDAT   12      // S - len(PILOTS)
#define VMAX   4       // max members per unit

#define THREADS       512
#define STAGES        6
#define CHUNK_ROWS    16
#define CHUNK_BYTES   (CHUNK_ROWS * NN * 4)      // 16384
#define STAGE_BYTES   (2 * CHUNK_BYTES)          // 32768 (cr + ci)
#define NCHUNK        16                         // 256 rows / 16
#define SMEM_TOTAL    (STAGES * STAGE_BYTES)     // 196608 dynamic (stages only)

#define WAIT_MBAR(mb, ph)                                                     \
    asm volatile("{\n\t.reg .pred P;\n\t"                                     \
                 "WL_%=:\n\t"                                                 \
                 "mbarrier.try_wait.parity.acquire.cta.shared::cta.b64 P, [%0], %1, 0x989680;\n\t" \
                 "@P bra WD_%=;\n\t"                                          \
                 "bra WL_%=;\n\t"                                             \
                 "WD_%=:\n\t}"                                                \
                 :: "r"(mb), "r"(ph) : "memory")

__device__ __forceinline__ void tma_chunk(uint32_t dst, const float* src,
                                          uint32_t mb)
{
    asm volatile("cp.async.bulk.shared::cluster.global.mbarrier::complete_tx::bytes "
                 "[%0], [%1], %2, [%3];"
                 :: "r"(dst), "l"(src), "r"((uint32_t)CHUNK_BYTES), "r"(mb)
                 : "memory");
}

// ---------------------------------------------------------------------------
// Grouped TMA streaming kernel, single launch.
// Grid = 112 blocks x 512 threads (1/SM). Block = one unit:
// (unique cov index, chunk of <=4 member bs, all 256 rows).
// 1) in-block grouping (scans over 112 entries)
// 2) TMA 6-stage x 32KB ring streams cov[group] ONCE (512 KB)
// 3) V member DFTs overlap the pipeline fill; member h -> registers
// 4) per chunk: warp w computes row w against all V h vectors
// ---------------------------------------------------------------------------
__global__ void __launch_bounds__(THREADS)
fused_kernel(const float* __restrict__ xr,
             const float* __restrict__ xi,
             const float* __restrict__ cr,
             const float* __restrict__ ci,
             const float* __restrict__ zr,
             const float* __restrict__ zi,
             const int*   __restrict__ shift,
             const int*   __restrict__ gidx,
             float*       __restrict__ out)
{
    extern __shared__ __align__(16) char smem[];
    uint32_t sb;
    asm("{ .reg .u64 t; cvta.to.shared.u64 t, %1; cvt.u32.u64 %0, t; }"
        : "=r"(sb) : "l"(smem));

    __shared__ int    s_idx[BS], s_rank[BS], s_cnt[BS], s_lead[BS];
    __shared__ int    s_map[2];
    __shared__ int    s_members[VMAX];
    __shared__ float2 xs[16 * 17];
    __shared__ float2 aa[17 * 16];
    __shared__ float2 hs[NN];
    __shared__ float2 w16[16];
    __shared__ uint64_t s_mbar[STAGES];

    const int tid  = threadIdx.x;
    const int w    = tid >> 5;
    const int lane = tid & 31;
    const int u    = blockIdx.x;

    if (tid < 16) {
        float sn, cs;
        sincospif(-(float)tid * 0.125f, &sn, &cs);   // e^{-2pi i t/16}
        w16[tid] = make_float2(cs, sn);
    }

    // ---- grouping: bs -> cov index, then lead/cnt/rank scans ----
    if (tid < BS) {
        const int b = tid / SS, s = tid % SS;
        const int g = __ldg(&gidx[s]);
        s_idx[tid]  = (g == 0) ? 0 : __ldg(&shift[b * NDAT + g - 1]);
    }
    __syncthreads();

    if (tid < BS) {
        const int mine = s_idx[tid];
        int ld = tid, rk = 0, c = 0;
        for (int t2 = 0; t2 < BS; t2++) {
            const int o = s_idx[t2];
            if (o == mine) {
                c++;
                if (t2 < tid) rk++;
                if (t2 < ld)  ld = t2;
            }
        }
        s_rank[tid] = rk;  s_cnt[tid] = c;  s_lead[tid] = ld;
    }
    __syncthreads();

    if (tid == 0) {
        int acc = 0, lb = -1, ch = 0;
        for (int t2 = 0; t2 < BS; t2++) {
            if (s_lead[t2] == t2) {
                const int nc = (s_cnt[t2] + VMAX - 1) / VMAX;
                if (u >= acc && u < acc + nc) { lb = t2; ch = u - acc; }
                acc += nc;
            }
        }
        s_map[0] = lb;  s_map[1] = ch;
    }
    __syncthreads();

    const int leadbs = s_map[0];
    if (leadbs < 0) return;                       // u >= NU: no work
    const int chunkm = s_map[1];
    const int covidx = s_idx[leadbs];
    const int V      = min(VMAX, s_cnt[leadbs] - chunkm * VMAX);

    if (tid < BS && s_idx[tid] == covidx) {
        const int r = s_rank[tid] - chunkm * VMAX;
        if (r >= 0 && r < VMAX) s_members[r] = tid;
    }
    __syncthreads();

    // ---- TMA: init mbarriers, fill all 6 stages up front (192 KB) ----
    const size_t base = (size_t)covidx * NN * NN;
    const float* crb  = cr + base;
    const float* cib  = ci + base;
    const uint32_t mbar0 = sb + (uint32_t)((const char*)s_mbar - smem);

    if (tid == 0) {
#pragma unroll
        for (int st = 0; st < STAGES; st++)
            asm volatile("mbarrier.init.shared.b64 [%0], %1;"
                         :: "r"(mbar0 + st * 8), "r"(1) : "memory");
        asm volatile("fence.proxy.async.shared::cta;" ::: "memory");
#pragma unroll
        for (int c = 0; c < STAGES; c++) {
            const uint32_t mb  = mbar0 + c * 8;
            const uint32_t dst = sb + c * STAGE_BYTES;
            asm volatile("mbarrier.arrive.expect_tx.shared.b64 _, [%0], %1;"
                         :: "r"(mb), "r"((uint32_t)STAGE_BYTES) : "memory");
            tma_chunk(dst,               crb + c * CHUNK_ROWS * NN, mb);
            tma_chunk(dst + CHUNK_BYTES, cib + c * CHUNK_ROWS * NN, mb);
        }
    }

    // ---- V member DFTs (overlap TMA fill); member h -> registers ----
    // hreg[v][0..3] = h[4*lane+j], hreg[v][4..7] = h[128+4*lane+j]
    float2 hreg[VMAX][8];

    for (int v = 0; v < V; v++) {
        const int bs = s_members[v];
        if (tid < NN)
            xs[(tid & 15) * 17 + (tid >> 4)] =
                make_float2(xr[bs * NN + tid], xi[bs * NN + tid]);
        __syncthreads();

        if (tid < NN) {   // stage A
            const int k0 = tid >> 4, n0 = tid & 15;
            float ar = 0.0f, ai = 0.0f;
#pragma unroll
            for (int n1 = 0; n1 < 16; n1++) {
                const float2 vv = xs[n0 * 17 + n1];
                const float2 ww = w16[(k0 * n1) & 15];
                ar = fmaf(vv.x, ww.x, fmaf(-vv.y, ww.y, ar));
                ai = fmaf(vv.x, ww.y, fmaf( vv.y, ww.x, ai));
            }
            float sn, cs;
            sincospif(-(float)(k0 * n0) * (1.0f / 128.0f), &sn, &cs);
            aa[n0 * 17 + k0] = make_float2(ar * cs - ai * sn,
                                           ar * sn + ai * cs);
        }
        __syncthreads();

        if (tid < NN) {   // stage B + conj(zc); m == tid
            const int k0 = tid & 15, k1 = tid >> 4;
            float Xr = 0.0f, Xi = 0.0f;
#pragma unroll
            for (int n0 = 0; n0 < 16; n0++) {
                const float2 vv = aa[n0 * 17 + k0];
                const float2 ww = w16[(k1 * n0) & 15];
                Xr = fmaf(vv.x, ww.x, fmaf(-vv.y, ww.y, Xr));
                Xi = fmaf(vv.x, ww.y, fmaf( vv.y, ww.x, Xi));
            }
            const float a  = zr[tid];
            const float bq = -zi[tid];
            hs[tid] = make_float2(Xr * a - Xi * bq, Xr * bq + Xi * a);
        }
        __syncthreads();

#pragma unroll
        for (int j = 0; j < 4; j++) {
            hreg[v][j]     = hs[4 * lane + j];
            hreg[v][4 + j] = hs[128 + 4 * lane + j];
        }
        __syncthreads();   // hs free for next v
    }

    const int ob0 = s_members[0] * NN;
    const int ob1 = (V > 1) ? s_members[1] * NN : 0;
    const int ob2 = (V > 2) ? s_members[2] * NN : 0;
    const int ob3 = (V > 3) ? s_members[3] * NN : 0;

    // ---- stream 16 chunks through the 6-stage ring ----
    int st = 0, ph = 0;
    for (int c = 0; c < NCHUNK; c++) {
        const uint32_t mb = mbar0 + st * 8;
        WAIT_MBAR(mb, (uint32_t)ph);

        const float4* crs = (const float4*)(smem + st * STAGE_BYTES) + w * 64;
        const float4* cis = crs + (CHUNK_BYTES / 16);

        const float4 a0 = crs[lane];
        const float4 a1 = crs[32 + lane];
        const float4 c0 = cis[lane];
        const float4 c1 = cis[32 + lane];

        float acc[VMAX];
#pragma unroll
        for (int v = 0; v < VMAX; v++) {
            float re = 0.0f;
            if (v < V) {
                re = fmaf(a0.x, hreg[v][0].x, fmaf(-c0.x, hreg[v][0].y, re));
                re = fmaf(a0.y, hreg[v][1].x, fmaf(-c0.y, hreg[v][1].y, re));
                re = fmaf(a0.z, hreg[v][2].x, fmaf(-c0.z, hreg[v][2].y, re));
                re = fmaf(a0.w, hreg[v][3].x, fmaf(-c0.w, hreg[v][3].y, re));
                re = fmaf(a1.x, hreg[v][4].x, fmaf(-c1.x, hreg[v][4].y, re));
                re = fmaf(a1.y, hreg[v][5].x, fmaf(-c1.y, hreg[v][5].y, re));
                re = fmaf(a1.z, hreg[v][6].x, fmaf(-c1.z, hreg[v][6].y, re));
                re = fmaf(a1.w, hreg[v][7].x, fmaf(-c1.w, hreg[v][7].y, re));
            }
            acc[v] = re;
        }

#pragma unroll
        for (int o = 16; o > 0; o >>= 1) {
#pragma unroll
            for (int v = 0; v < VMAX; v++)
                acc[v] += __shfl_xor_sync(0xffffffffu, acc[v], o);
        }

        if (lane == 0) {
            const int row = c * CHUNK_ROWS + w;
            out[ob0 + row] = acc[0];
            if (V > 1) out[ob1 + row] = acc[1];
            if (V > 2) out[ob2 + row] = acc[2];
            if (V > 3) out[ob3 + row] = acc[3];
        }

        __syncthreads();   // all warps done with this stage

        if (tid == 0 && c + STAGES < NCHUNK) {
            const int cn = c + STAGES;
            const uint32_t dst = sb + st * STAGE_BYTES;
            asm volatile("mbarrier.arrive.expect_tx.shared.b64 _, [%0], %1;"
                         :: "r"(mb), "r"((uint32_t)STAGE_BYTES) : "memory");
            tma_chunk(dst,               crb + cn * CHUNK_ROWS * NN, mb);
            tma_chunk(dst + CHUNK_BYTES, cib + cn * CHUNK_ROWS * NN, mb);
        }

        if (++st == STAGES) { st = 0; ph ^= 1; }
    }
}

extern "C" void kernel_launch(void* const* d_in, const int* in_sizes, int n_in,
                              void* d_out, int out_size)
{
    const float* xr    = (const float*)d_in[0];
    const float* xi    = (const float*)d_in[1];
    const float* cr    = (const float*)d_in[2];
    const float* ci    = (const float*)d_in[3];
    const float* zr    = (const float*)d_in[4];
    const float* zi    = (const float*)d_in[5];
    const int*   shift = (const int*)d_in[6];
    const int*   gidx  = (const int*)d_in[7];

    cudaFuncSetAttribute(fused_kernel,
                         cudaFuncAttributeMaxDynamicSharedMemorySize,
                         SMEM_TOTAL);

    fused_kernel<<<BS, THREADS, SMEM_TOTAL>>>(xr, xi, cr, ci, zr, zi,
                                              shift, gidx, (float*)d_out);
}